// round 14
// baseline (speedup 1.0000x reference)
#include <cuda_runtime.h>
#include <cuda_fp16.h>
#include <cmath>
#include <cstdint>

// ------------------------------------------------------------------
// Problem constants
// ------------------------------------------------------------------
#define B_     16
#define N_     577
#define C_     768
#define HEADS_ 12
#define HD_    64
#define HID_   3072
#define M_     (B_ * N_)        // 9232 rows

// ------------------------------------------------------------------
// Static scratch
// ------------------------------------------------------------------
__device__ __half g_h   [M_ * C_];      // LN outputs (fp16)
__device__ __half g_qkv [M_ * 3 * C_];  // QKV (fp16)
__device__ __half g_att [M_ * C_];      // attention output (fp16)
__device__ float  g_x1  [M_ * C_];      // post-attention residual (fp32)
__device__ __half g_fc1 [M_ * HID_];    // GELU(fc1) (fp16)
// fp16 transposed weights: [N][K], k-contiguous
__device__ __half g_wTq [3 * C_ * C_];
__device__ __half g_wTp [C_ * C_];
__device__ __half g_wT1 [HID_ * C_];
__device__ __half g_wT2 [C_ * HID_];

// ------------------------------------------------------------------
// LayerNorm (fp32 in, fp16 out)
// ------------------------------------------------------------------
__global__ void ln_kernel(const float* __restrict__ x,
                          const float* __restrict__ g,
                          const float* __restrict__ b,
                          __half* __restrict__ out) {
    int row = blockIdx.x;
    const float* xr = x + (size_t)row * C_;
    float sum = 0.f, sumsq = 0.f;
    for (int i = threadIdx.x; i < C_; i += blockDim.x) {
        float v = xr[i];
        sum += v; sumsq += v * v;
    }
    __shared__ float s1[8], s2[8];
    for (int o = 16; o; o >>= 1) {
        sum   += __shfl_down_sync(0xffffffffu, sum, o);
        sumsq += __shfl_down_sync(0xffffffffu, sumsq, o);
    }
    int wid = threadIdx.x >> 5, lid = threadIdx.x & 31;
    if (lid == 0) { s1[wid] = sum; s2[wid] = sumsq; }
    __syncthreads();
    if (wid == 0) {
        sum   = (lid < 8) ? s1[lid] : 0.f;
        sumsq = (lid < 8) ? s2[lid] : 0.f;
        for (int o = 4; o; o >>= 1) {
            sum   += __shfl_down_sync(0xffffffffu, sum, o);
            sumsq += __shfl_down_sync(0xffffffffu, sumsq, o);
        }
        if (lid == 0) { s1[0] = sum; s2[0] = sumsq; }
    }
    __syncthreads();
    float mu   = s1[0] * (1.f / C_);
    float var  = s2[0] * (1.f / C_) - mu * mu;
    float rstd = rsqrtf(var + 1e-5f);
    __half* orow = out + (size_t)row * C_;
    for (int i = threadIdx.x; i < C_; i += blockDim.x)
        orow[i] = __float2half((xr[i] - mu) * rstd * g[i] + b[i]);
}

// ------------------------------------------------------------------
// transpose + fp32->fp16: in[R][Ccol] -> out[Ccol][R]
// ------------------------------------------------------------------
__global__ void convT(const float* __restrict__ in, __half* __restrict__ out,
                      int R, int Ccol) {
    __shared__ float t[32][33];
    int bx = blockIdx.x * 32, by = blockIdx.y * 32;
    int tx = threadIdx.x, ty = threadIdx.y;   // 32 x 8
#pragma unroll
    for (int j = 0; j < 32; j += 8)
        t[ty + j][tx] = in[(size_t)(by + ty + j) * Ccol + bx + tx];
    __syncthreads();
#pragma unroll
    for (int j = 0; j < 32; j += 8)
        out[(size_t)(bx + ty + j) * R + by + tx] = __float2half(t[tx][ty + j]);
}

// ------------------------------------------------------------------
// helpers
// ------------------------------------------------------------------
__device__ __forceinline__ void mma_f16(float* d, const uint32_t* a, const uint32_t* b) {
    asm volatile(
        "mma.sync.aligned.m16n8k16.row.col.f32.f16.f16.f32 "
        "{%0,%1,%2,%3}, {%4,%5,%6,%7}, {%8,%9}, {%0,%1,%2,%3};"
        : "+f"(d[0]), "+f"(d[1]), "+f"(d[2]), "+f"(d[3])
        : "r"(a[0]), "r"(a[1]), "r"(a[2]), "r"(a[3]), "r"(b[0]), "r"(b[1]));
}

__device__ __forceinline__ void ldsm_x4(uint32_t& r0, uint32_t& r1, uint32_t& r2, uint32_t& r3,
                                        uint32_t addr) {
    asm volatile("ldmatrix.sync.aligned.m8n8.x4.shared.b16 {%0,%1,%2,%3}, [%4];"
                 : "=r"(r0), "=r"(r1), "=r"(r2), "=r"(r3) : "r"(addr));
}

__device__ __forceinline__ void ldsm_x4t(uint32_t& r0, uint32_t& r1, uint32_t& r2, uint32_t& r3,
                                         uint32_t addr) {
    asm volatile("ldmatrix.sync.aligned.m8n8.x4.trans.shared.b16 {%0,%1,%2,%3}, [%4];"
                 : "=r"(r0), "=r"(r1), "=r"(r2), "=r"(r3) : "r"(addr));
}

__device__ __forceinline__ void cp_async16(uint32_t dst_smem, const void* src, bool pred) {
    int sz = pred ? 16 : 0;
    asm volatile("cp.async.cg.shared.global [%0], [%1], 16, %2;"
                 :: "r"(dst_smem), "l"(src), "r"(sz));
}

__device__ __forceinline__ float fexp(float x) {
    x = fmaxf(x, -80.f);
    float y = x * 1.4426950408889634f;
    float t = y + 12582912.f;
    int   i = __float_as_int(t) << 23;
    float f = y - (t - 12582912.f);
    float p = 1.3333558146e-3f;
    p = fmaf(p, f, 9.6181291076e-3f);
    p = fmaf(p, f, 5.5504108665e-2f);
    p = fmaf(p, f, 2.4022650696e-1f);
    p = fmaf(p, f, 6.9314718056e-1f);
    p = fmaf(p, f, 1.0f);
    return __int_as_float(__float_as_int(p) + i);
}

// ------------------------------------------------------------------
// fp16 tensor-core GEMM: C = epi(A[MxK] @ BT[NxK]^T + bias [, + res])
// R10 engine (256 thr, 2x4 warps, 64x32 warp tile) with BK=64:
// half the barriers, 2x longer unrolled LDSM/MMA window per stage.
// Smem: XOR-swizzled 128B rows (chunk*16 ^ (row&7)*16), 3 stages,
// 96KB -> still 2 CTAs/SM.
// ------------------------------------------------------------------
#define EPI_BIAS      0
#define EPI_BIAS_RES  1
#define EPI_BIAS_GELU 2

#define OPER_BYTES (128 * 128)               // 16384 per operand (BK=64 fp16)
#define STAGE_BYTES (2 * OPER_BYTES)         // 32768
#define GEMM_SMEM (3 * STAGE_BYTES)          // 98304

template <int EPI, int OUTH>
__global__ __launch_bounds__(256)
void gemm_h(const __half* __restrict__ A, const __half* __restrict__ BT,
            const float* __restrict__ bias, const float* __restrict__ res,
            void* __restrict__ Cout, int M, int N, int K) {
    extern __shared__ char smem[];

    const int tid  = threadIdx.x;
    const int wid  = tid >> 5, lane = tid & 31;
    const int wm   = wid >> 2, wn = wid & 3;
    const int row0 = blockIdx.y * 128, col0 = blockIdx.x * 128;

    float acc[4][4][4];
#pragma unroll
    for (int i = 0; i < 4; i++)
#pragma unroll
        for (int j = 0; j < 4; j++)
#pragma unroll
            for (int t = 0; t < 4; t++) acc[i][j][t] = 0.f;

    const int nIter = K / 64;

    // 128 rows x 8 chunks (16B) per operand = 1024 chunks; 4 per thread.
    auto load_stage = [&](int it, int s) {
        char* base = smem + s * STAGE_BYTES;
        int k0 = it * 64;
#pragma unroll
        for (int p = 0; p < 4; p++) {
            int ci  = tid + p * 256;
            int row = ci >> 3, c16 = ci & 7;
            uint32_t sw = (uint32_t)(c16 * 16) ^ (uint32_t)((row & 7) * 16);
            cp_async16((uint32_t)__cvta_generic_to_shared(base) + (uint32_t)(row * 128) + sw,
                       A + (size_t)(row0 + row) * K + k0 + c16 * 8, (row0 + row) < M);
            cp_async16((uint32_t)__cvta_generic_to_shared(base) + OPER_BYTES
                           + (uint32_t)(row * 128) + sw,
                       BT + (size_t)(col0 + row) * K + k0 + c16 * 8, true);
        }
        asm volatile("cp.async.commit_group;");
    };

    load_stage(0, 0);
    if (nIter > 1) load_stage(1, 1);

    const int a_row = wm * 64 + (lane & 15);
    const int a_ch  = lane >> 4;                      // 0/1
    const int a_xr  = (a_row & 7) * 16;
    const int b_row = wn * 32 + (lane & 7) + (lane >> 4) * 8;
    const int b_ch  = (lane >> 3) & 1;
    const int b_xr  = (b_row & 7) * 16;

    int stage = 0;
    for (int it = 0; it < nIter; ++it) {
        if (it + 1 < nIter) {
            asm volatile("cp.async.wait_group 1;");
        } else {
            asm volatile("cp.async.wait_group 0;");
        }
        __syncthreads();
        if (it + 2 < nIter) load_stage(it + 2, (stage + 2) % 3);

        uint32_t abase = (uint32_t)__cvta_generic_to_shared(smem + stage * STAGE_BYTES);
        uint32_t bbase = abase + OPER_BYTES;

#pragma unroll
        for (int ks = 0; ks < 4; ks++) {
            uint32_t af[4][4], bf[4][2];
#pragma unroll
            for (int mt = 0; mt < 4; mt++)
                ldsm_x4(af[mt][0], af[mt][1], af[mt][2], af[mt][3],
                        abase + (uint32_t)((a_row + mt * 16) * 128
                                           + (((2 * ks + a_ch) * 16) ^ a_xr)));
#pragma unroll
            for (int np = 0; np < 2; np++)
                ldsm_x4(bf[2 * np][0], bf[2 * np][1], bf[2 * np + 1][0], bf[2 * np + 1][1],
                        bbase + (uint32_t)((b_row + np * 16) * 128
                                           + (((2 * ks + b_ch) * 16) ^ b_xr)));
#pragma unroll
            for (int mt = 0; mt < 4; mt++)
#pragma unroll
                for (int nt = 0; nt < 4; nt++)
                    mma_f16(acc[mt][nt], af[mt], bf[nt]);
        }
        stage = (stage + 1) % 3;
    }

    // ---- epilogue ----
    const int fr = lane >> 2, fc = lane & 3;
    const int c2 = fc * 2;
#pragma unroll
    for (int mt = 0; mt < 4; mt++) {
#pragma unroll
        for (int half = 0; half < 2; half++) {
            int row = row0 + wm * 64 + mt * 16 + fr + half * 8;
            if (row >= M) continue;
#pragma unroll
            for (int nt = 0; nt < 4; nt++) {
                int col = col0 + wn * 32 + nt * 8 + c2;
                float v0 = acc[mt][nt][half * 2 + 0] + bias[col];
                float v1 = acc[mt][nt][half * 2 + 1] + bias[col + 1];
                if (EPI == EPI_BIAS_RES) {
                    v0 += res[(size_t)row * N + col];
                    v1 += res[(size_t)row * N + col + 1];
                }
                if (EPI == EPI_BIAS_GELU) {
                    v0 = 0.5f * v0 * (1.f + erff(v0 * 0.70710678118654752f));
                    v1 = 0.5f * v1 * (1.f + erff(v1 * 0.70710678118654752f));
                }
                if (OUTH) {
                    *reinterpret_cast<__half2*>((__half*)Cout + (size_t)row * N + col) =
                        __floats2half2_rn(v0, v1);
                } else {
                    *reinterpret_cast<float2*>((float*)Cout + (size_t)row * N + col) =
                        make_float2(v0, v1);
                }
            }
        }
    }
}

// ------------------------------------------------------------------
// fp16 tensor-core flash attention (unchanged from R10, passing)
// ------------------------------------------------------------------
#define AT_ROW 144
#define AT_Q 0
#define AT_K (128 * AT_ROW)
#define AT_V (AT_K + 64 * AT_ROW)
#define AT_P (AT_V + 64 * AT_ROW)
#define ATTN_SMEM (AT_P + 8 * 16 * AT_ROW)   // 55296

__global__ __launch_bounds__(256, 2)
void attn_h(const __half* __restrict__ qkv, __half* __restrict__ out) {
    extern __shared__ char smc[];
    const uint32_t sbase = (uint32_t)__cvta_generic_to_shared(smc);

    const int tid  = threadIdx.x;
    const int wid  = tid >> 5, lane = tid & 31;
    const int fr   = lane >> 2, fc = lane & 3;
    const int qt   = blockIdx.x, h = blockIdx.y, b = blockIdx.z;

    const __half* qbase = qkv + (size_t)(b * N_) * (3 * C_) + h * HD_;

    {
#pragma unroll
        for (int p = 0; p < 4; p++) {
            int ci  = tid + p * 256;
            int row = ci >> 3, c = ci & 7;
            int n   = qt * 128 + row;
            cp_async16(sbase + AT_Q + row * AT_ROW + c * 16,
                       qbase + (size_t)n * (3 * C_) + c * 8, n < N_);
        }
    }

    auto load_kv = [&](int j0) {
#pragma unroll
        for (int p = 0; p < 2; p++) {
            int ci  = tid + p * 256;
            int row = ci >> 3, c = ci & 7;
            int n   = j0 + row;
            const __half* src = qbase + (size_t)n * (3 * C_) + c * 8;
            cp_async16(sbase + AT_K + row * AT_ROW + c * 16, src + C_,     n < N_);
            cp_async16(sbase + AT_V + row * AT_ROW + c * 16, src + 2 * C_, n < N_);
        }
        asm volatile("cp.async.commit_group;");
    };

    load_kv(0);
    asm volatile("cp.async.wait_group 0;");
    __syncthreads();

    const int a_row = wid * 16 + (lane & 15);
    const int a_ch  = lane >> 4;
    const int b_row = (lane & 7) + (lane >> 4) * 8;
    const int b_ch  = (lane >> 3) & 1;
    const uint32_t pb = sbase + AT_P + wid * (16 * AT_ROW);

    float O[8][4];
#pragma unroll
    for (int nf = 0; nf < 8; nf++)
#pragma unroll
        for (int t = 0; t < 4; t++) O[nf][t] = 0.f;
    float m0 = -1e30f, m1 = -1e30f, l0 = 0.f, l1 = 0.f;

    const int NT = (N_ + 63) / 64;

    for (int jt = 0; jt < NT; jt++) {
        const int j0 = jt * 64;

        float S[8][4];
#pragma unroll
        for (int nf = 0; nf < 8; nf++)
#pragma unroll
            for (int t = 0; t < 4; t++) S[nf][t] = 0.f;

#pragma unroll
        for (int ks = 0; ks < 4; ks++) {
            uint32_t af[4], bf[8][2];
            ldsm_x4(af[0], af[1], af[2], af[3],
                    sbase + AT_Q + (uint32_t)(a_row * AT_ROW + (a_ch + 2 * ks) * 16));
#pragma unroll
            for (int np = 0; np < 4; np++)
                ldsm_x4(bf[2 * np][0], bf[2 * np][1], bf[2 * np + 1][0], bf[2 * np + 1][1],
                        sbase + AT_K + (uint32_t)((b_row + np * 16) * AT_ROW + (2 * ks + b_ch) * 16));
#pragma unroll
            for (int nf = 0; nf < 8; nf++)
                mma_f16(S[nf], af, bf[nf]);
        }

        float mt0 = -1e30f, mt1 = -1e30f;
#pragma unroll
        for (int nf = 0; nf < 8; nf++) {
            int jb = j0 + nf * 8 + 2 * fc;
            float s0 = S[nf][0] * 0.125f, s1 = S[nf][1] * 0.125f;
            float s2 = S[nf][2] * 0.125f, s3 = S[nf][3] * 0.125f;
            if (jb     >= N_) { s0 = -1e30f; s2 = -1e30f; }
            if (jb + 1 >= N_) { s1 = -1e30f; s3 = -1e30f; }
            S[nf][0] = s0; S[nf][1] = s1; S[nf][2] = s2; S[nf][3] = s3;
            mt0 = fmaxf(mt0, fmaxf(s0, s1));
            mt1 = fmaxf(mt1, fmaxf(s2, s3));
        }
        mt0 = fmaxf(mt0, __shfl_xor_sync(0xffffffffu, mt0, 1));
        mt0 = fmaxf(mt0, __shfl_xor_sync(0xffffffffu, mt0, 2));
        mt1 = fmaxf(mt1, __shfl_xor_sync(0xffffffffu, mt1, 1));
        mt1 = fmaxf(mt1, __shfl_xor_sync(0xffffffffu, mt1, 2));

        float mn0 = fmaxf(m0, mt0), mn1 = fmaxf(m1, mt1);
        float f0 = fexp(m0 - mn0),  f1 = fexp(m1 - mn1);
        m0 = mn0; m1 = mn1;
        l0 *= f0; l1 *= f1;

        float ls0 = 0.f, ls1 = 0.f;
#pragma unroll
        for (int nf = 0; nf < 8; nf++) {
            float p0 = fexp(S[nf][0] - mn0);
            float p1 = fexp(S[nf][1] - mn0);
            float p2 = fexp(S[nf][2] - mn1);
            float p3 = fexp(S[nf][3] - mn1);
            ls0 += p0 + p1; ls1 += p2 + p3;
            O[nf][0] *= f0; O[nf][1] *= f0; O[nf][2] *= f1; O[nf][3] *= f1;
            int cb = (nf * 8 + 2 * fc) * 2;
            *reinterpret_cast<__half2*>(smc + AT_P + wid * (16 * AT_ROW) + fr * AT_ROW + cb) =
                __floats2half2_rn(p0, p1);
            *reinterpret_cast<__half2*>(smc + AT_P + wid * (16 * AT_ROW) + (fr + 8) * AT_ROW + cb) =
                __floats2half2_rn(p2, p3);
        }
        l0 += ls0; l1 += ls1;
        __syncwarp();

#pragma unroll
        for (int ks = 0; ks < 4; ks++) {
            uint32_t af[4], bf[8][2];
            ldsm_x4(af[0], af[1], af[2], af[3],
                    pb + (uint32_t)((lane & 15) * AT_ROW + ((lane >> 4) + 2 * ks) * 16));
#pragma unroll
            for (int np = 0; np < 4; np++)
                ldsm_x4t(bf[2 * np][0], bf[2 * np][1], bf[2 * np + 1][0], bf[2 * np + 1][1],
                         sbase + AT_V + (uint32_t)((ks * 16 + (lane & 15)) * AT_ROW
                                                   + (np * 16 + ((lane >> 4) << 3)) * 2));
#pragma unroll
            for (int nf = 0; nf < 8; nf++)
                mma_f16(O[nf], af, bf[nf]);
        }

        __syncthreads();
        if (jt + 1 < NT) {
            load_kv(j0 + 64);
            asm volatile("cp.async.wait_group 0;");
            __syncthreads();
        }
    }

    l0 += __shfl_xor_sync(0xffffffffu, l0, 1);
    l0 += __shfl_xor_sync(0xffffffffu, l0, 2);
    l1 += __shfl_xor_sync(0xffffffffu, l1, 1);
    l1 += __shfl_xor_sync(0xffffffffu, l1, 2);
    float inv0 = 1.f / l0, inv1 = 1.f / l1;

    int n0r = qt * 128 + wid * 16 + fr;
    int n1r = n0r + 8;
    __half* obase = out + (size_t)(b * N_) * C_ + h * HD_;
    if (n0r < N_) {
#pragma unroll
        for (int nf = 0; nf < 8; nf++) {
            int col = nf * 8 + 2 * fc;
            *reinterpret_cast<__half2*>(&obase[(size_t)n0r * C_ + col]) =
                __floats2half2_rn(O[nf][0] * inv0, O[nf][1] * inv0);
        }
    }
    if (n1r < N_) {
#pragma unroll
        for (int nf = 0; nf < 8; nf++) {
            int col = nf * 8 + 2 * fc;
            *reinterpret_cast<__half2*>(&obase[(size_t)n1r * C_ + col]) =
                __floats2half2_rn(O[nf][2] * inv1, O[nf][3] * inv1);
        }
    }
}

// ------------------------------------------------------------------
// Launch
// ------------------------------------------------------------------
extern "C" void kernel_launch(void* const* d_in, const int* in_sizes, int n_in,
                              void* d_out, int out_size) {
    const float* x      = (const float*)d_in[0];
    const float* ln1_g  = (const float*)d_in[1];
    const float* ln1_b  = (const float*)d_in[2];
    const float* w_qkv  = (const float*)d_in[3];
    const float* b_qkv  = (const float*)d_in[4];
    const float* w_proj = (const float*)d_in[5];
    const float* b_proj = (const float*)d_in[6];
    const float* ln2_g  = (const float*)d_in[7];
    const float* ln2_b  = (const float*)d_in[8];
    const float* w_fc1  = (const float*)d_in[9];
    const float* b_fc1  = (const float*)d_in[10];
    const float* w_fc2  = (const float*)d_in[11];
    const float* b_fc2  = (const float*)d_in[12];
    float* out = (float*)d_out;

    __half *h, *qkv, *att, *fc1, *wTq, *wTp, *wT1, *wT2;
    float *x1;
    cudaGetSymbolAddress((void**)&h,   g_h);
    cudaGetSymbolAddress((void**)&qkv, g_qkv);
    cudaGetSymbolAddress((void**)&att, g_att);
    cudaGetSymbolAddress((void**)&x1,  g_x1);
    cudaGetSymbolAddress((void**)&fc1, g_fc1);
    cudaGetSymbolAddress((void**)&wTq, g_wTq);
    cudaGetSymbolAddress((void**)&wTp, g_wTp);
    cudaGetSymbolAddress((void**)&wT1, g_wT1);
    cudaGetSymbolAddress((void**)&wT2, g_wT2);

    static bool attr_done = false;
    if (!attr_done) {
        cudaFuncSetAttribute(gemm_h<EPI_BIAS, 1>,
                             cudaFuncAttributeMaxDynamicSharedMemorySize, GEMM_SMEM);
        cudaFuncSetAttribute(gemm_h<EPI_BIAS_RES, 0>,
                             cudaFuncAttributeMaxDynamicSharedMemorySize, GEMM_SMEM);
        cudaFuncSetAttribute(gemm_h<EPI_BIAS_GELU, 1>,
                             cudaFuncAttributeMaxDynamicSharedMemorySize, GEMM_SMEM);
        cudaFuncSetAttribute(attn_h,
                             cudaFuncAttributeMaxDynamicSharedMemorySize, ATTN_SMEM);
        attr_done = true;
    }

    const int MB = (M_ + 127) / 128;   // 73
    dim3 tb(32, 8);

    // 0) weights -> fp16 [N][K]
    convT<<<dim3(3 * C_ / 32, C_ / 32), tb>>>(w_qkv,  wTq, C_,   3 * C_);
    convT<<<dim3(C_ / 32,     C_ / 32), tb>>>(w_proj, wTp, C_,   C_);
    convT<<<dim3(HID_ / 32,   C_ / 32), tb>>>(w_fc1,  wT1, C_,   HID_);
    convT<<<dim3(C_ / 32,   HID_ / 32), tb>>>(w_fc2,  wT2, HID_, C_);

    // 1) LN1 (fp16 out)
    ln_kernel<<<M_, 256>>>(x, ln1_g, ln1_b, h);
    // 2) QKV = h @ w_qkv + b_qkv  (fp16 out)
    gemm_h<EPI_BIAS, 1><<<dim3(3 * C_ / 128, MB), 256, GEMM_SMEM>>>(
        h, wTq, b_qkv, nullptr, qkv, M_, 3 * C_, C_);
    // 3) attention (fp16 in/out)
    attn_h<<<dim3((N_ + 127) / 128, HEADS_, B_), 256, ATTN_SMEM>>>(qkv, att);
    // 4) x1 = x + att @ w_proj + b_proj  (fp32 out)
    gemm_h<EPI_BIAS_RES, 0><<<dim3(C_ / 128, MB), 256, GEMM_SMEM>>>(
        att, wTp, b_proj, x, x1, M_, C_, C_);
    // 5) LN2 (fp16 out)
    ln_kernel<<<M_, 256>>>(x1, ln2_g, ln2_b, h);
    // 6) fc1 = gelu(h @ w_fc1 + b_fc1)  (fp16 out)
    gemm_h<EPI_BIAS_GELU, 1><<<dim3(HID_ / 128, MB), 256, GEMM_SMEM>>>(
        h, wT1, b_fc1, nullptr, fc1, M_, HID_, C_);
    // 7) out = x1 + fc1 @ w_fc2 + b_fc2  (fp32 out)
    gemm_h<EPI_BIAS_RES, 0><<<dim3(C_ / 128, MB), 256, GEMM_SMEM>>>(
        fc1, wT2, b_fc2, x1, out, M_, C_, HID_);
}

// round 17
// speedup vs baseline: 1.3271x; 1.3271x over previous
#include <cuda_runtime.h>
#include <cuda_fp16.h>
#include <cmath>
#include <cstdint>

// ------------------------------------------------------------------
// Problem constants
// ------------------------------------------------------------------
#define B_     16
#define N_     577
#define C_     768
#define HEADS_ 12
#define HD_    64
#define HID_   3072
#define M_     (B_ * N_)        // 9232 rows

// ------------------------------------------------------------------
// Static scratch
// ------------------------------------------------------------------
__device__ __half g_h   [M_ * C_];      // LN outputs (fp16)
__device__ __half g_qkv [M_ * 3 * C_];  // QKV (fp16)
__device__ __half g_att [M_ * C_];      // attention output (fp16)
__device__ float  g_x1  [M_ * C_];      // post-attention residual (fp32)
__device__ __half g_fc1 [M_ * HID_];    // GELU(fc1) (fp16)
// fp16 transposed weights: [N][K], k-contiguous
__device__ __half g_wTq [3 * C_ * C_];
__device__ __half g_wTp [C_ * C_];
__device__ __half g_wT1 [HID_ * C_];
__device__ __half g_wT2 [C_ * HID_];

// ------------------------------------------------------------------
// LayerNorm (fp32 in, fp16 out). blockDim=256, C_=768 -> each thread
// caches its 3 elements in registers (single pass over gmem).
// ------------------------------------------------------------------
__global__ void ln_kernel(const float* __restrict__ x,
                          const float* __restrict__ g,
                          const float* __restrict__ b,
                          __half* __restrict__ out) {
    int row = blockIdx.x;
    const float* xr = x + (size_t)row * C_;
    int t = threadIdx.x;
    float v0 = xr[t], v1 = xr[t + 256], v2 = xr[t + 512];
    float sum   = v0 + v1 + v2;
    float sumsq = v0 * v0 + v1 * v1 + v2 * v2;
    __shared__ float s1[8], s2[8];
    for (int o = 16; o; o >>= 1) {
        sum   += __shfl_down_sync(0xffffffffu, sum, o);
        sumsq += __shfl_down_sync(0xffffffffu, sumsq, o);
    }
    int wid = t >> 5, lid = t & 31;
    if (lid == 0) { s1[wid] = sum; s2[wid] = sumsq; }
    __syncthreads();
    if (wid == 0) {
        sum   = (lid < 8) ? s1[lid] : 0.f;
        sumsq = (lid < 8) ? s2[lid] : 0.f;
        for (int o = 4; o; o >>= 1) {
            sum   += __shfl_down_sync(0xffffffffu, sum, o);
            sumsq += __shfl_down_sync(0xffffffffu, sumsq, o);
        }
        if (lid == 0) { s1[0] = sum; s2[0] = sumsq; }
    }
    __syncthreads();
    float mu   = s1[0] * (1.f / C_);
    float var  = s2[0] * (1.f / C_) - mu * mu;
    float rstd = rsqrtf(var + 1e-5f);
    __half* orow = out + (size_t)row * C_;
    orow[t]       = __float2half((v0 - mu) * rstd * g[t]       + b[t]);
    orow[t + 256] = __float2half((v1 - mu) * rstd * g[t + 256] + b[t + 256]);
    orow[t + 512] = __float2half((v2 - mu) * rstd * g[t + 512] + b[t + 512]);
}

// ------------------------------------------------------------------
// Fused transpose+convert for ALL four weights in ONE launch.
// 32x32 tiles; blockIdx.x range-dispatches the four jobs.
//   job0: w_qkv  [768][2304] -> 72*24 = 1728 tiles  (cum 1728)
//   job1: w_proj [768][768]  -> 24*24 =  576 tiles  (cum 2304)
//   job2: w_fc1  [768][3072] -> 96*24 = 2304 tiles  (cum 4608)
//   job3: w_fc2  [3072][768] -> 24*96 = 2304 tiles  (cum 6912)
// ------------------------------------------------------------------
#define CVT_BLOCKS 6912
__global__ void convT_all(const float* __restrict__ w0, const float* __restrict__ w1,
                          const float* __restrict__ w2, const float* __restrict__ w3,
                          __half* __restrict__ o0, __half* __restrict__ o1,
                          __half* __restrict__ o2, __half* __restrict__ o3) {
    int bid = blockIdx.x;
    const float* in; __half* out; int R, Ccol, t;
    if (bid < 1728)      { in = w0; out = o0; R = 768;  Ccol = 2304; t = bid; }
    else if (bid < 2304) { in = w1; out = o1; R = 768;  Ccol = 768;  t = bid - 1728; }
    else if (bid < 4608) { in = w2; out = o2; R = 768;  Ccol = 3072; t = bid - 2304; }
    else                 { in = w3; out = o3; R = 3072; Ccol = 768;  t = bid - 4608; }
    int tilesX = Ccol >> 5;
    int bx = (t % tilesX) * 32, by = (t / tilesX) * 32;

    __shared__ float tl[32][33];
    int tx = threadIdx.x, ty = threadIdx.y;   // 32 x 8
#pragma unroll
    for (int j = 0; j < 32; j += 8)
        tl[ty + j][tx] = in[(size_t)(by + ty + j) * Ccol + bx + tx];
    __syncthreads();
#pragma unroll
    for (int j = 0; j < 32; j += 8)
        out[(size_t)(bx + ty + j) * R + by + tx] = __float2half(tl[tx][ty + j]);
}

// ------------------------------------------------------------------
// helpers
// ------------------------------------------------------------------
__device__ __forceinline__ void mma_f16(float* d, const uint32_t* a, const uint32_t* b) {
    asm volatile(
        "mma.sync.aligned.m16n8k16.row.col.f32.f16.f16.f32 "
        "{%0,%1,%2,%3}, {%4,%5,%6,%7}, {%8,%9}, {%0,%1,%2,%3};"
        : "+f"(d[0]), "+f"(d[1]), "+f"(d[2]), "+f"(d[3])
        : "r"(a[0]), "r"(a[1]), "r"(a[2]), "r"(a[3]), "r"(b[0]), "r"(b[1]));
}

__device__ __forceinline__ void ldsm_x4(uint32_t& r0, uint32_t& r1, uint32_t& r2, uint32_t& r3,
                                        uint32_t addr) {
    asm volatile("ldmatrix.sync.aligned.m8n8.x4.shared.b16 {%0,%1,%2,%3}, [%4];"
                 : "=r"(r0), "=r"(r1), "=r"(r2), "=r"(r3) : "r"(addr));
}

__device__ __forceinline__ void ldsm_x4t(uint32_t& r0, uint32_t& r1, uint32_t& r2, uint32_t& r3,
                                         uint32_t addr) {
    asm volatile("ldmatrix.sync.aligned.m8n8.x4.trans.shared.b16 {%0,%1,%2,%3}, [%4];"
                 : "=r"(r0), "=r"(r1), "=r"(r2), "=r"(r3) : "r"(addr));
}

__device__ __forceinline__ void cp_async16(uint32_t dst_smem, const void* src, bool pred) {
    int sz = pred ? 16 : 0;
    asm volatile("cp.async.cg.shared.global [%0], [%1], 16, %2;"
                 :: "r"(dst_smem), "l"(src), "r"(sz));
}

__device__ __forceinline__ float fexp(float x) {
    x = fmaxf(x, -80.f);
    float y = x * 1.4426950408889634f;
    float t = y + 12582912.f;
    int   i = __float_as_int(t) << 23;
    float f = y - (t - 12582912.f);
    float p = 1.3333558146e-3f;
    p = fmaf(p, f, 9.6181291076e-3f);
    p = fmaf(p, f, 5.5504108665e-2f);
    p = fmaf(p, f, 2.4022650696e-1f);
    p = fmaf(p, f, 6.9314718056e-1f);
    p = fmaf(p, f, 1.0f);
    return __int_as_float(__float_as_int(p) + i);
}

// ------------------------------------------------------------------
// fp16 tensor-core GEMM — EXACT R10/658us engine.
// 256 threads, 2x4 warps, warp tile 64x32, BK=32, 80B padded rows,
// 3-stage cp.async pipeline.
// ------------------------------------------------------------------
#define EPI_BIAS      0
#define EPI_BIAS_RES  1
#define EPI_BIAS_GELU 2

#define ROW_B 80
#define OPER_BYTES (128 * ROW_B)
#define STAGE_BYTES (2 * OPER_BYTES)
#define GEMM_SMEM (3 * STAGE_BYTES)   // 61440

template <int EPI, int OUTH>
__global__ __launch_bounds__(256)
void gemm_h(const __half* __restrict__ A, const __half* __restrict__ BT,
            const float* __restrict__ bias, const float* __restrict__ res,
            void* __restrict__ Cout, int M, int N, int K) {
    extern __shared__ char smem[];

    const int tid  = threadIdx.x;
    const int wid  = tid >> 5, lane = tid & 31;
    const int wm   = wid >> 2, wn = wid & 3;
    const int row0 = blockIdx.y * 128, col0 = blockIdx.x * 128;

    float acc[4][4][4];
#pragma unroll
    for (int i = 0; i < 4; i++)
#pragma unroll
        for (int j = 0; j < 4; j++)
#pragma unroll
            for (int t = 0; t < 4; t++) acc[i][j][t] = 0.f;

    const int nIter = K / 32;

    auto load_stage = [&](int it, int s) {
        char* base = smem + s * STAGE_BYTES;
        int k0 = it * 32;
#pragma unroll
        for (int p = 0; p < 2; p++) {
            int ci  = tid + p * 256;
            int row = ci >> 2, c16 = ci & 3;
            uint32_t dst = (uint32_t)__cvta_generic_to_shared(base + row * ROW_B + c16 * 16);
            cp_async16(dst, A + (size_t)(row0 + row) * K + k0 + c16 * 8, (row0 + row) < M);
        }
#pragma unroll
        for (int p = 0; p < 2; p++) {
            int ci  = tid + p * 256;
            int row = ci >> 2, c16 = ci & 3;
            uint32_t dst = (uint32_t)__cvta_generic_to_shared(
                base + OPER_BYTES + row * ROW_B + c16 * 16);
            cp_async16(dst, BT + (size_t)(col0 + row) * K + k0 + c16 * 8, true);
        }
        asm volatile("cp.async.commit_group;");
    };

    load_stage(0, 0);
    if (nIter > 1) load_stage(1, 1);

    const int a_row = wm * 64 + (lane & 15);
    const int a_ch  = lane >> 4;
    const int b_row = wn * 32 + (lane & 7) + (lane >> 4) * 8;
    const int b_ch  = (lane >> 3) & 1;

    int stage = 0;
    for (int it = 0; it < nIter; ++it) {
        if (it + 1 < nIter) {
            asm volatile("cp.async.wait_group 1;");
        } else {
            asm volatile("cp.async.wait_group 0;");
        }
        __syncthreads();
        if (it + 2 < nIter) load_stage(it + 2, (stage + 2) % 3);

        uint32_t abase = (uint32_t)__cvta_generic_to_shared(smem + stage * STAGE_BYTES);
        uint32_t bbase = abase + OPER_BYTES;

#pragma unroll
        for (int ks = 0; ks < 2; ks++) {
            uint32_t af[4][4], bf[4][2];
#pragma unroll
            for (int mt = 0; mt < 4; mt++)
                ldsm_x4(af[mt][0], af[mt][1], af[mt][2], af[mt][3],
                        abase + (uint32_t)((a_row + mt * 16) * ROW_B + (a_ch + 2 * ks) * 16));
#pragma unroll
            for (int np = 0; np < 2; np++)
                ldsm_x4(bf[2 * np][0], bf[2 * np][1], bf[2 * np + 1][0], bf[2 * np + 1][1],
                        bbase + (uint32_t)((b_row + np * 16) * ROW_B + (2 * ks + b_ch) * 16));
#pragma unroll
            for (int mt = 0; mt < 4; mt++)
#pragma unroll
                for (int nt = 0; nt < 4; nt++)
                    mma_f16(acc[mt][nt], af[mt], bf[nt]);
        }
        stage = (stage + 1) % 3;
    }

    const int fr = lane >> 2, fc = lane & 3;
    const int c2 = fc * 2;
#pragma unroll
    for (int mt = 0; mt < 4; mt++) {
#pragma unroll
        for (int half = 0; half < 2; half++) {
            int row = row0 + wm * 64 + mt * 16 + fr + half * 8;
            if (row >= M) continue;
#pragma unroll
            for (int nt = 0; nt < 4; nt++) {
                int col = col0 + wn * 32 + nt * 8 + c2;
                float v0 = acc[mt][nt][half * 2 + 0] + bias[col];
                float v1 = acc[mt][nt][half * 2 + 1] + bias[col + 1];
                if (EPI == EPI_BIAS_RES) {
                    v0 += res[(size_t)row * N + col];
                    v1 += res[(size_t)row * N + col + 1];
                }
                if (EPI == EPI_BIAS_GELU) {
                    v0 = 0.5f * v0 * (1.f + erff(v0 * 0.70710678118654752f));
                    v1 = 0.5f * v1 * (1.f + erff(v1 * 0.70710678118654752f));
                }
                if (OUTH) {
                    *reinterpret_cast<__half2*>((__half*)Cout + (size_t)row * N + col) =
                        __floats2half2_rn(v0, v1);
                } else {
                    *reinterpret_cast<float2*>((float*)Cout + (size_t)row * N + col) =
                        make_float2(v0, v1);
                }
            }
        }
    }
}

// ------------------------------------------------------------------
// fp16 tensor-core flash attention (EXACT R10/658us version)
// ------------------------------------------------------------------
#define AT_ROW 144
#define AT_Q 0
#define AT_K (128 * AT_ROW)
#define AT_V (AT_K + 64 * AT_ROW)
#define AT_P (AT_V + 64 * AT_ROW)
#define ATTN_SMEM (AT_P + 8 * 16 * AT_ROW)   // 55296

__global__ __launch_bounds__(256, 2)
void attn_h(const __half* __restrict__ qkv, __half* __restrict__ out) {
    extern __shared__ char smc[];
    const uint32_t sbase = (uint32_t)__cvta_generic_to_shared(smc);

    const int tid  = threadIdx.x;
    const int wid  = tid >> 5, lane = tid & 31;
    const int fr   = lane >> 2, fc = lane & 3;
    const int qt   = blockIdx.x, h = blockIdx.y, b = blockIdx.z;

    const __half* qbase = qkv + (size_t)(b * N_) * (3 * C_) + h * HD_;

    {
#pragma unroll
        for (int p = 0; p < 4; p++) {
            int ci  = tid + p * 256;
            int row = ci >> 3, c = ci & 7;
            int n   = qt * 128 + row;
            cp_async16(sbase + AT_Q + row * AT_ROW + c * 16,
                       qbase + (size_t)n * (3 * C_) + c * 8, n < N_);
        }
    }

    auto load_kv = [&](int j0) {
#pragma unroll
        for (int p = 0; p < 2; p++) {
            int ci  = tid + p * 256;
            int row = ci >> 3, c = ci & 7;
            int n   = j0 + row;
            const __half* src = qbase + (size_t)n * (3 * C_) + c * 8;
            cp_async16(sbase + AT_K + row * AT_ROW + c * 16, src + C_,     n < N_);
            cp_async16(sbase + AT_V + row * AT_ROW + c * 16, src + 2 * C_, n < N_);
        }
        asm volatile("cp.async.commit_group;");
    };

    load_kv(0);
    asm volatile("cp.async.wait_group 0;");
    __syncthreads();

    const int a_row = wid * 16 + (lane & 15);
    const int a_ch  = lane >> 4;
    const int b_row = (lane & 7) + (lane >> 4) * 8;
    const int b_ch  = (lane >> 3) & 1;
    const uint32_t pb = sbase + AT_P + wid * (16 * AT_ROW);

    float O[8][4];
#pragma unroll
    for (int nf = 0; nf < 8; nf++)
#pragma unroll
        for (int t = 0; t < 4; t++) O[nf][t] = 0.f;
    float m0 = -1e30f, m1 = -1e30f, l0 = 0.f, l1 = 0.f;

    const int NT = (N_ + 63) / 64;

    for (int jt = 0; jt < NT; jt++) {
        const int j0 = jt * 64;

        float S[8][4];
#pragma unroll
        for (int nf = 0; nf < 8; nf++)
#pragma unroll
            for (int t = 0; t < 4; t++) S[nf][t] = 0.f;

#pragma unroll
        for (int ks = 0; ks < 4; ks++) {
            uint32_t af[4], bf[8][2];
            ldsm_x4(af[0], af[1], af[2], af[3],
                    sbase + AT_Q + (uint32_t)(a_row * AT_ROW + (a_ch + 2 * ks) * 16));
#pragma unroll
            for (int np = 0; np < 4; np++)
                ldsm_x4(bf[2 * np][0], bf[2 * np][1], bf[2 * np + 1][0], bf[2 * np + 1][1],
                        sbase + AT_K + (uint32_t)((b_row + np * 16) * AT_ROW + (2 * ks + b_ch) * 16));
#pragma unroll
            for (int nf = 0; nf < 8; nf++)
                mma_f16(S[nf], af, bf[nf]);
        }

        float mt0 = -1e30f, mt1 = -1e30f;
#pragma unroll
        for (int nf = 0; nf < 8; nf++) {
            int jb = j0 + nf * 8 + 2 * fc;
            float s0 = S[nf][0] * 0.125f, s1 = S[nf][1] * 0.125f;
            float s2 = S[nf][2] * 0.125f, s3 = S[nf][3] * 0.125f;
            if (jb     >= N_) { s0 = -1e30f; s2 = -1e30f; }
            if (jb + 1 >= N_) { s1 = -1e30f; s3 = -1e30f; }
            S[nf][0] = s0; S[nf][1] = s1; S[nf][2] = s2; S[nf][3] = s3;
            mt0 = fmaxf(mt0, fmaxf(s0, s1));
            mt1 = fmaxf(mt1, fmaxf(s2, s3));
        }
        mt0 = fmaxf(mt0, __shfl_xor_sync(0xffffffffu, mt0, 1));
        mt0 = fmaxf(mt0, __shfl_xor_sync(0xffffffffu, mt0, 2));
        mt1 = fmaxf(mt1, __shfl_xor_sync(0xffffffffu, mt1, 1));
        mt1 = fmaxf(mt1, __shfl_xor_sync(0xffffffffu, mt1, 2));

        float mn0 = fmaxf(m0, mt0), mn1 = fmaxf(m1, mt1);
        float f0 = fexp(m0 - mn0),  f1 = fexp(m1 - mn1);
        m0 = mn0; m1 = mn1;
        l0 *= f0; l1 *= f1;

        float ls0 = 0.f, ls1 = 0.f;
#pragma unroll
        for (int nf = 0; nf < 8; nf++) {
            float p0 = fexp(S[nf][0] - mn0);
            float p1 = fexp(S[nf][1] - mn0);
            float p2 = fexp(S[nf][2] - mn1);
            float p3 = fexp(S[nf][3] - mn1);
            ls0 += p0 + p1; ls1 += p2 + p3;
            O[nf][0] *= f0; O[nf][1] *= f0; O[nf][2] *= f1; O[nf][3] *= f1;
            int cb = (nf * 8 + 2 * fc) * 2;
            *reinterpret_cast<__half2*>(smc + AT_P + wid * (16 * AT_ROW) + fr * AT_ROW + cb) =
                __floats2half2_rn(p0, p1);
            *reinterpret_cast<__half2*>(smc + AT_P + wid * (16 * AT_ROW) + (fr + 8) * AT_ROW + cb) =
                __floats2half2_rn(p2, p3);
        }
        l0 += ls0; l1 += ls1;
        __syncwarp();

#pragma unroll
        for (int ks = 0; ks < 4; ks++) {
            uint32_t af[4], bf[8][2];
            ldsm_x4(af[0], af[1], af[2], af[3],
                    pb + (uint32_t)((lane & 15) * AT_ROW + ((lane >> 4) + 2 * ks) * 16));
#pragma unroll
            for (int np = 0; np < 4; np++)
                ldsm_x4t(bf[2 * np][0], bf[2 * np][1], bf[2 * np + 1][0], bf[2 * np + 1][1],
                         sbase + AT_V + (uint32_t)((ks * 16 + (lane & 15)) * AT_ROW
                                                   + (np * 16 + ((lane >> 4) << 3)) * 2));
#pragma unroll
            for (int nf = 0; nf < 8; nf++)
                mma_f16(O[nf], af, bf[nf]);
        }

        __syncthreads();
        if (jt + 1 < NT) {
            load_kv(j0 + 64);
            asm volatile("cp.async.wait_group 0;");
            __syncthreads();
        }
    }

    l0 += __shfl_xor_sync(0xffffffffu, l0, 1);
    l0 += __shfl_xor_sync(0xffffffffu, l0, 2);
    l1 += __shfl_xor_sync(0xffffffffu, l1, 1);
    l1 += __shfl_xor_sync(0xffffffffu, l1, 2);
    float inv0 = 1.f / l0, inv1 = 1.f / l1;

    int n0r = qt * 128 + wid * 16 + fr;
    int n1r = n0r + 8;
    __half* obase = out + (size_t)(b * N_) * C_ + h * HD_;
    if (n0r < N_) {
#pragma unroll
        for (int nf = 0; nf < 8; nf++) {
            int col = nf * 8 + 2 * fc;
            *reinterpret_cast<__half2*>(&obase[(size_t)n0r * C_ + col]) =
                __floats2half2_rn(O[nf][0] * inv0, O[nf][1] * inv0);
        }
    }
    if (n1r < N_) {
#pragma unroll
        for (int nf = 0; nf < 8; nf++) {
            int col = nf * 8 + 2 * fc;
            *reinterpret_cast<__half2*>(&obase[(size_t)n1r * C_ + col]) =
                __floats2half2_rn(O[nf][2] * inv1, O[nf][3] * inv1);
        }
    }
}

// ------------------------------------------------------------------
// Launch
// ------------------------------------------------------------------
extern "C" void kernel_launch(void* const* d_in, const int* in_sizes, int n_in,
                              void* d_out, int out_size) {
    const float* x      = (const float*)d_in[0];
    const float* ln1_g  = (const float*)d_in[1];
    const float* ln1_b  = (const float*)d_in[2];
    const float* w_qkv  = (const float*)d_in[3];
    const float* b_qkv  = (const float*)d_in[4];
    const float* w_proj = (const float*)d_in[5];
    const float* b_proj = (const float*)d_in[6];
    const float* ln2_g  = (const float*)d_in[7];
    const float* ln2_b  = (const float*)d_in[8];
    const float* w_fc1  = (const float*)d_in[9];
    const float* b_fc1  = (const float*)d_in[10];
    const float* w_fc2  = (const float*)d_in[11];
    const float* b_fc2  = (const float*)d_in[12];
    float* out = (float*)d_out;

    __half *h, *qkv, *att, *fc1, *wTq, *wTp, *wT1, *wT2;
    float *x1;
    cudaGetSymbolAddress((void**)&h,   g_h);
    cudaGetSymbolAddress((void**)&qkv, g_qkv);
    cudaGetSymbolAddress((void**)&att, g_att);
    cudaGetSymbolAddress((void**)&x1,  g_x1);
    cudaGetSymbolAddress((void**)&fc1, g_fc1);
    cudaGetSymbolAddress((void**)&wTq, g_wTq);
    cudaGetSymbolAddress((void**)&wTp, g_wTp);
    cudaGetSymbolAddress((void**)&wT1, g_wT1);
    cudaGetSymbolAddress((void**)&wT2, g_wT2);

    static bool attr_done = false;
    if (!attr_done) {
        cudaFuncSetAttribute(gemm_h<EPI_BIAS, 1>,
                             cudaFuncAttributeMaxDynamicSharedMemorySize, GEMM_SMEM);
        cudaFuncSetAttribute(gemm_h<EPI_BIAS_RES, 0>,
                             cudaFuncAttributeMaxDynamicSharedMemorySize, GEMM_SMEM);
        cudaFuncSetAttribute(gemm_h<EPI_BIAS_GELU, 1>,
                             cudaFuncAttributeMaxDynamicSharedMemorySize, GEMM_SMEM);
        cudaFuncSetAttribute(attn_h,
                             cudaFuncAttributeMaxDynamicSharedMemorySize, ATTN_SMEM);
        attr_done = true;
    }

    const int MB = (M_ + 127) / 128;   // 73

    // 0) all four weights -> fp16 [N][K] in ONE launch
    convT_all<<<CVT_BLOCKS, dim3(32, 8)>>>(w_qkv, w_proj, w_fc1, w_fc2,
                                           wTq, wTp, wT1, wT2);

    // 1) LN1 (fp16 out)
    ln_kernel<<<M_, 256>>>(x, ln1_g, ln1_b, h);
    // 2) QKV = h @ w_qkv + b_qkv  (fp16 out)
    gemm_h<EPI_BIAS, 1><<<dim3(3 * C_ / 128, MB), 256, GEMM_SMEM>>>(
        h, wTq, b_qkv, nullptr, qkv, M_, 3 * C_, C_);
    // 3) attention (fp16 in/out)
    attn_h<<<dim3((N_ + 127) / 128, HEADS_, B_), 256, ATTN_SMEM>>>(qkv, att);
    // 4) x1 = x + att @ w_proj + b_proj  (fp32 out)
    gemm_h<EPI_BIAS_RES, 0><<<dim3(C_ / 128, MB), 256, GEMM_SMEM>>>(
        att, wTp, b_proj, x, x1, M_, C_, C_);
    // 5) LN2 (fp16 out)
    ln_kernel<<<M_, 256>>>(x1, ln2_g, ln2_b, h);
    // 6) fc1 = gelu(h @ w_fc1 + b_fc1)  (fp16 out)
    gemm_h<EPI_BIAS_GELU, 1><<<dim3(HID_ / 128, MB), 256, GEMM_SMEM>>>(
        h, wT1, b_fc1, nullptr, fc1, M_, HID_, C_);
    // 7) out = x1 + fc1 @ w_fc2 + b_fc2  (fp32 out)
    gemm_h<EPI_BIAS_RES, 0><<<dim3(C_ / 128, MB), 256, GEMM_SMEM>>>(
        fc1, wT2, b_fc2, x1, out, M_, C_, HID_);
}